// round 5
// baseline (speedup 1.0000x reference)
#include <cuda_runtime.h>

#define N_NODES 50000
#define N_EDGES 800000
#define DIM 96

typedef unsigned long long ull;

// Scratch (__device__ globals per allocation-free rule)
__device__ __align__(128) float g_agg[N_NODES * DIM];   // 19.2 MB
__device__ float g_deg[N_NODES];

// ---------------------------------------------------------------------------
// GEMM tiling (per half: K = 96)
// ---------------------------------------------------------------------------
#define BM 64
#define BN 96
#define BK 32
#define TM 8
#define TN 4
#define GEMM_THREADS 192
#define GEMM_BLOCKS ((N_NODES + BM - 1) / BM)   // 782
#define APITCH (BK + 2)
#define BPITCH (BK / 2 + 1)

// Scatter geometry: 6 warps/block, 4 edges/warp -> 24 edges/block
#define EDGES_PER_WARP 4
#define EDGES_PER_BLOCK (6 * EDGES_PER_WARP)
#define SCATTER_BLOCKS ((N_EDGES + EDGES_PER_BLOCK - 1) / EDGES_PER_BLOCK)

__device__ __forceinline__ void ffma2(ull& d, ull a, ull b) {
    asm("fma.rn.f32x2 %0, %1, %2, %0;" : "+l"(d) : "l"(a), "l"(b));
}

// ---------------------------------------------------------------------------
// Shared GEMM body. NEIGH=false: A=x, out = A@W^T + bias (store).
// NEIGH=true:  A=g_agg scaled by 1/max(deg,1), out += A@W^T + bias.
// ---------------------------------------------------------------------------
template <bool NEIGH>
__device__ __forceinline__ void gemm_body(int blockId,
                                          const float* __restrict__ A,
                                          const float* __restrict__ W,
                                          const float* __restrict__ bias,
                                          float* __restrict__ out) {
    __shared__ float  sA[BM][APITCH];
    __shared__ float2 sB[BN][BPITCH];

    const int tid = threadIdx.x;
    const int tx = tid % (BN / TN);    // 0..23 column group
    const int ty = tid / (BN / TN);    // 0..7  row group
    const int rowBase = blockId * BM;

    ull acc2[TM][TN];
    #pragma unroll
    for (int i = 0; i < TM; i++)
        #pragma unroll
        for (int j = 0; j < TN; j++) acc2[i][j] = 0ULL;

    for (int k0 = 0; k0 < DIM; k0 += BK) {
        // stage A: 64 rows x 32 k = 512 float4s over 192 threads
        #pragma unroll
        for (int idx = tid; idx < BM * BK / 4; idx += GEMM_THREADS) {
            int m  = idx >> 3;
            int kq = idx & 7;
            int row = rowBase + m;
            float4 v = make_float4(0.f, 0.f, 0.f, 0.f);
            if (row < N_NODES) {
                v = ((const float4*)(A + (size_t)row * DIM + k0))[kq];
                if (NEIGH) {
                    float inv = 1.0f / fmaxf(g_deg[row], 1.0f);
                    v.x *= inv; v.y *= inv; v.z *= inv; v.w *= inv;
                }
            }
            sA[m][kq * 4 + 0] = v.x;
            sA[m][kq * 4 + 1] = v.y;
            sA[m][kq * 4 + 2] = v.z;
            sA[m][kq * 4 + 3] = v.w;
        }
        // stage B: W is [j][k] row-major, k-contiguous pairs
        #pragma unroll
        for (int idx = tid; idx < BN * (BK / 2); idx += GEMM_THREADS) {
            int j  = idx / (BK / 2);
            int kp = idx % (BK / 2);
            sB[j][kp] = *(const float2*)(W + (size_t)j * DIM + k0 + 2 * kp);
        }
        __syncthreads();

        #pragma unroll
        for (int kp = 0; kp < BK / 2; kp++) {
            ull a2[TM], b2[TN];
            #pragma unroll
            for (int i = 0; i < TM; i++)
                a2[i] = *(const ull*)&sA[ty * TM + i][2 * kp];
            #pragma unroll
            for (int j = 0; j < TN; j++)
                b2[j] = *(const ull*)&sB[tx * TN + j][kp];
            #pragma unroll
            for (int i = 0; i < TM; i++)
                #pragma unroll
                for (int j = 0; j < TN; j++)
                    ffma2(acc2[i][j], a2[i], b2[j]);
        }
        __syncthreads();
    }

    const int colBase = tx * TN;
    float4 bv = *(const float4*)(bias + colBase);

    #pragma unroll
    for (int i = 0; i < TM; i++) {
        int row = rowBase + ty * TM + i;
        if (row < N_NODES) {
            float r[TN];
            #pragma unroll
            for (int j = 0; j < TN; j++) {
                ull u = acc2[i][j];
                r[j] = __uint_as_float((unsigned)(u & 0xffffffffu)) +
                       __uint_as_float((unsigned)(u >> 32));
            }
            float4 v;
            float* op = out + (size_t)row * DIM + colBase;
            if (NEIGH) {
                float4 prev = *(float4*)op;
                v.x = prev.x + r[0] + bv.x;
                v.y = prev.y + r[1] + bv.y;
                v.z = prev.z + r[2] + bv.z;
                v.w = prev.w + r[3] + bv.w;
            } else {
                v.x = r[0] + bv.x;
                v.y = r[1] + bv.y;
                v.z = r[2] + bv.z;
                v.w = r[3] + bv.w;
            }
            *(float4*)op = v;
        }
    }
}

// ---------------------------------------------------------------------------
// Kernel A: blocks [0, GEMM_BLOCKS) do the self-GEMM; the rest scatter edges.
// Scatter: warp handles 4 edges x 24 float4-chunks = 96 chunks in 3 passes,
// all 32 lanes active.
// ---------------------------------------------------------------------------
__global__ __launch_bounds__(GEMM_THREADS, 3)
void fused_kernel(const float* __restrict__ x,
                  const int* __restrict__ edge_index,
                  const float* __restrict__ Ws,
                  const float* __restrict__ bs,
                  float* __restrict__ out) {
    if (blockIdx.x < GEMM_BLOCKS) {
        gemm_body<false>(blockIdx.x, x, Ws, bs, out);
        return;
    }
    // ---- scatter part ----
    int sb = blockIdx.x - GEMM_BLOCKS;
    int warp = threadIdx.x >> 5;
    int lane = threadIdx.x & 31;
    int e0 = (sb * 6 + warp) * EDGES_PER_WARP;

    #pragma unroll
    for (int it = 0; it < 3; it++) {
        int idx = it * 32 + lane;         // 0..95
        int el  = idx / 24;               // local edge 0..3
        int c   = idx % 24;               // chunk 0..23
        int e   = e0 + el;
        if (e < N_EDGES) {
            int src = __ldg(&edge_index[e]);
            int dst = __ldg(&edge_index[N_EDGES + e]);
            float4 v = ((const float4*)(x + (size_t)src * DIM))[c];
            float* p = g_agg + (size_t)dst * DIM + c * 4;
            asm volatile("red.global.add.v4.f32 [%0], {%1,%2,%3,%4};"
                         :: "l"(p), "f"(v.x), "f"(v.y), "f"(v.z), "f"(v.w)
                         : "memory");
            if (c == 0) atomicAdd(&g_deg[dst], 1.0f);
        }
    }
}

// ---------------------------------------------------------------------------
// Kernel B: neighbor-half GEMM, accumulates into out.
// ---------------------------------------------------------------------------
__global__ __launch_bounds__(GEMM_THREADS, 3)
void neigh_kernel(const float* __restrict__ Wn,
                  const float* __restrict__ bn,
                  float* __restrict__ out) {
    gemm_body<true>(blockIdx.x, g_agg, Wn, bn, out);
}

// ---------------------------------------------------------------------------
extern "C" void kernel_launch(void* const* d_in, const int* in_sizes, int n_in,
                              void* d_out, int out_size) {
    const float* x        = (const float*)d_in[0];
    const int*   ei       = (const int*)d_in[1];
    const float* W_self   = (const float*)d_in[2];
    const float* b_self   = (const float*)d_in[3];
    const float* W_neigh  = (const float*)d_in[4];
    const float* b_neigh  = (const float*)d_in[5];
    float*       out      = (float*)d_out;

    static void* agg_ptr = nullptr;
    static void* deg_ptr = nullptr;
    if (!agg_ptr) {
        cudaGetSymbolAddress(&agg_ptr, g_agg);
        cudaGetSymbolAddress(&deg_ptr, g_deg);
    }

    cudaMemsetAsync(agg_ptr, 0, (size_t)N_NODES * DIM * sizeof(float));
    cudaMemsetAsync(deg_ptr, 0, (size_t)N_NODES * sizeof(float));

    fused_kernel<<<GEMM_BLOCKS + SCATTER_BLOCKS, GEMM_THREADS>>>(x, ei, W_self,
                                                                 b_self, out);
    neigh_kernel<<<GEMM_BLOCKS, GEMM_THREADS>>>(W_neigh, b_neigh, out);
}

// round 6
// speedup vs baseline: 1.1308x; 1.1308x over previous
#include <cuda_runtime.h>

#define N_NODES 50000
#define N_EDGES 800000
#define DIM 96

typedef unsigned long long ull;

// Scratch (__device__ globals per allocation-free rule)
__device__ __align__(128) float g_agg[N_NODES * DIM];   // 19.2 MB
__device__ float g_deg[N_NODES];

// ---------------------------------------------------------------------------
// Kernel: edge scatter — one thread per (edge, 16B chunk). 24 chunks/edge.
// 128-bit vector reduction (red.global.add.v4.f32, sm_90+).
// ---------------------------------------------------------------------------
__global__ void scatter_kernel(const float* __restrict__ x,
                               const int* __restrict__ edge_index) {
    long long t = (long long)blockIdx.x * blockDim.x + threadIdx.x;
    int e = (int)(t / 24);
    int c = (int)(t % 24);
    if (e >= N_EDGES) return;

    int src = edge_index[e];            // edge_index[0][e]
    int dst = edge_index[N_EDGES + e];  // edge_index[1][e]

    float4 v = ((const float4*)(x + (size_t)src * DIM))[c];
    float* p = g_agg + (size_t)dst * DIM + c * 4;
    asm volatile("red.global.add.v4.f32 [%0], {%1,%2,%3,%4};"
                 :: "l"(p), "f"(v.x), "f"(v.y), "f"(v.z), "f"(v.w) : "memory");
    if (c == 0) atomicAdd(&g_deg[dst], 1.0f);
}

// ---------------------------------------------------------------------------
// GEMM: out = [x | g_agg/deg] @ [Ws | Wn]^T + (bs+bn)
// BM=64, BN=96, full K=96 per stage (2 stages), 384 threads, 4x4 thread tile,
// packed fma.rn.f32x2 accumulators carried across both stages.
// ---------------------------------------------------------------------------
#define BM 64
#define BN 96
#define TM 4
#define TN 4
#define GEMM_THREADS 384
#define GEMM_BLOCKS ((N_NODES + BM - 1) / BM)   // 782
#define APITCH 98   // floats; 392B row stride (8B-aligned pairs)
#define BPITCH 49   // float2; 392B row stride

__device__ __forceinline__ void ffma2(ull& d, ull a, ull b) {
    asm("fma.rn.f32x2 %0, %1, %2, %0;" : "+l"(d) : "l"(a), "l"(b));
}

__global__ void gemm_kernel(const float* __restrict__ x,
                            const float* __restrict__ Ws,
                            const float* __restrict__ bs,
                            const float* __restrict__ Wn,
                            const float* __restrict__ bn,
                            float* __restrict__ out) {
    __shared__ __align__(16) float  sA[BM][APITCH];   // 25.1 KB
    __shared__ __align__(16) float2 sB[BN][BPITCH];   // 37.6 KB

    const int tid = threadIdx.x;
    const int tx = tid % (BN / TN);    // 0..23 column group
    const int ty = tid / (BN / TN);    // 0..15 row group
    const int rowBase = blockIdx.x * BM;

    ull acc2[TM][TN];
    #pragma unroll
    for (int i = 0; i < TM; i++)
        #pragma unroll
        for (int j = 0; j < TN; j++) acc2[i][j] = 0ULL;

    #pragma unroll 1
    for (int stage = 0; stage < 2; stage++) {
        const float* __restrict__ A = stage ? g_agg : x;
        const float* __restrict__ W = stage ? Wn : Ws;
        if (stage) __syncthreads();    // protect smem reuse

        // stage A: 64 rows x 96 cols = 1536 float4 over 384 threads (4 each)
        #pragma unroll
        for (int it = 0; it < 4; it++) {
            int idx = tid + it * GEMM_THREADS;
            int m = idx / 24, q = idx % 24;
            int row = rowBase + m;
            float4 v = make_float4(0.f, 0.f, 0.f, 0.f);
            if (row < N_NODES) {
                v = ((const float4*)(A + (size_t)row * DIM))[q];
                if (stage) {
                    float inv = 1.0f / fmaxf(g_deg[row], 1.0f);
                    v.x *= inv; v.y *= inv; v.z *= inv; v.w *= inv;
                }
            }
            sA[m][q * 4 + 0] = v.x;
            sA[m][q * 4 + 1] = v.y;
            sA[m][q * 4 + 2] = v.z;
            sA[m][q * 4 + 3] = v.w;
        }
        // stage B: 96 rows x 96 k = 2304 float4 over 384 threads (6 each)
        #pragma unroll
        for (int it = 0; it < 6; it++) {
            int idx = tid + it * GEMM_THREADS;
            int j = idx / 24, q = idx % 24;
            float4 v = *(const float4*)(W + (size_t)j * DIM + q * 4);
            sB[j][2 * q + 0] = make_float2(v.x, v.y);
            sB[j][2 * q + 1] = make_float2(v.z, v.w);
        }
        __syncthreads();

        #pragma unroll 6
        for (int kp = 0; kp < DIM / 2; kp++) {
            ull a2[TM], b2[TN];
            #pragma unroll
            for (int i = 0; i < TM; i++)
                a2[i] = *(const ull*)&sA[ty * TM + i][2 * kp];
            #pragma unroll
            for (int j = 0; j < TN; j++)
                b2[j] = *(const ull*)&sB[tx * TN + j][kp];
            #pragma unroll
            for (int i = 0; i < TM; i++)
                #pragma unroll
                for (int j = 0; j < TN; j++)
                    ffma2(acc2[i][j], a2[i], b2[j]);
        }
    }

    // epilogue: reduce pair sums, fused bias, float4 stores
    const int colBase = tx * TN;
    float4 bias;
    bias.x = bs[colBase + 0] + bn[colBase + 0];
    bias.y = bs[colBase + 1] + bn[colBase + 1];
    bias.z = bs[colBase + 2] + bn[colBase + 2];
    bias.w = bs[colBase + 3] + bn[colBase + 3];

    #pragma unroll
    for (int i = 0; i < TM; i++) {
        int row = rowBase + ty * TM + i;
        if (row < N_NODES) {
            float r[TN];
            #pragma unroll
            for (int j = 0; j < TN; j++) {
                ull u = acc2[i][j];
                r[j] = __uint_as_float((unsigned)(u & 0xffffffffu)) +
                       __uint_as_float((unsigned)(u >> 32));
            }
            float4 v;
            v.x = r[0] + bias.x;
            v.y = r[1] + bias.y;
            v.z = r[2] + bias.z;
            v.w = r[3] + bias.w;
            *(float4*)(out + (size_t)row * DIM + colBase) = v;
        }
    }
}

// ---------------------------------------------------------------------------
extern "C" void kernel_launch(void* const* d_in, const int* in_sizes, int n_in,
                              void* d_out, int out_size) {
    const float* x        = (const float*)d_in[0];
    const int*   ei       = (const int*)d_in[1];
    const float* W_self   = (const float*)d_in[2];
    const float* b_self   = (const float*)d_in[3];
    const float* W_neigh  = (const float*)d_in[4];
    const float* b_neigh  = (const float*)d_in[5];
    float*       out      = (float*)d_out;

    static void* agg_ptr = nullptr;
    static void* deg_ptr = nullptr;
    if (!agg_ptr) {
        cudaGetSymbolAddress(&agg_ptr, g_agg);
        cudaGetSymbolAddress(&deg_ptr, g_deg);
    }

    cudaMemsetAsync(agg_ptr, 0, (size_t)N_NODES * DIM * sizeof(float));
    cudaMemsetAsync(deg_ptr, 0, (size_t)N_NODES * sizeof(float));

    {
        long long total = (long long)N_EDGES * 24;
        int blocks = (int)((total + 255) / 256);
        scatter_kernel<<<blocks, 256>>>(x, ei);
    }

    gemm_kernel<<<GEMM_BLOCKS, GEMM_THREADS>>>(x, W_self, b_self,
                                               W_neigh, b_neigh, out);
}

// round 7
// speedup vs baseline: 1.5085x; 1.3340x over previous
#include <cuda_runtime.h>

#define N_NODES 50000
#define N_EDGES 800000
#define DIM 96

typedef unsigned long long ull;

// Scratch (__device__ globals per allocation-free rule)
__device__ __align__(128) float g_agg[N_NODES * DIM];   // 19.2 MB
__device__ float g_deg[N_NODES];

// ---------------------------------------------------------------------------
// Scatter: one thread per (edge, float4 chunk); 24 chunks/edge.
// red.global.add.v4.f32 into g_agg (L2-resident). LTS-cap bound (~50us).
// ---------------------------------------------------------------------------
__global__ void scatter_kernel(const float* __restrict__ x,
                               const int* __restrict__ edge_index) {
    long long t = (long long)blockIdx.x * blockDim.x + threadIdx.x;
    int e = (int)(t / 24);
    int c = (int)(t % 24);
    if (e >= N_EDGES) return;

    int src = edge_index[e];
    int dst = edge_index[N_EDGES + e];

    float4 v = ((const float4*)(x + (size_t)src * DIM))[c];
    float* p = g_agg + (size_t)dst * DIM + c * 4;
    asm volatile("red.global.add.v4.f32 [%0], {%1,%2,%3,%4};"
                 :: "l"(p), "f"(v.x), "f"(v.y), "f"(v.z), "f"(v.w) : "memory");
    if (c == 0) atomicAdd(&g_deg[dst], 1.0f);
}

// ---------------------------------------------------------------------------
// GEMM half: out(+)= A @ W^T + bias.  BM=64, BN=96, full K=96 single stage.
// 128 threads, thread tile TM=8 x TN=6, packed fma.rn.f32x2.
// NEIGH: A = g_agg scaled by 1/max(deg,1); accumulate into out.
// ---------------------------------------------------------------------------
#define BM 64
#define BN 96
#define TM 8
#define TN 6
#define GT 128
#define GEMM_BLOCKS ((N_NODES + BM - 1) / BM)   // 782
#define APITCH 100   // floats: 400B rows, float4-aligned
#define BPITCH 49    // float2: 392B rows -> <=2-way LDS conflicts

__device__ __forceinline__ void ffma2(ull& d, ull a, ull b) {
    asm("fma.rn.f32x2 %0, %1, %2, %0;" : "+l"(d) : "l"(a), "l"(b));
}

template <bool NEIGH>
__global__ void gemm_half(const float* __restrict__ A,
                          const float* __restrict__ W,
                          const float* __restrict__ bias,
                          float* __restrict__ out) {
    __shared__ __align__(16) float  sA[BM][APITCH];   // 25.6 KB
    __shared__ __align__(16) float2 sB[BN][BPITCH];   // 37.6 KB
    __shared__ float sInv[BM];

    const int tid = threadIdx.x;
    const int tx = tid % (BN / TN);     // 0..15 column group
    const int ty = tid / (BN / TN);     // 0..7  row group
    const int rowBase = blockIdx.x * BM;

    if (NEIGH) {
        if (tid < BM) {
            int row = rowBase + tid;
            float d = (row < N_NODES) ? g_deg[row] : 1.0f;
            sInv[tid] = 1.0f / fmaxf(d, 1.0f);
        }
        __syncthreads();
    }

    // stage A: 64 rows x 24 float4 = 1536 loads over 128 threads (12 each)
    #pragma unroll
    for (int it = 0; it < 12; it++) {
        int idx = tid + it * GT;
        int m = idx / 24, q = idx % 24;
        int row = rowBase + m;
        float4 v = make_float4(0.f, 0.f, 0.f, 0.f);
        if (row < N_NODES) {
            v = ((const float4*)(A + (size_t)row * DIM))[q];
            if (NEIGH) {
                float inv = sInv[m];
                v.x *= inv; v.y *= inv; v.z *= inv; v.w *= inv;
            }
        }
        ((float4*)&sA[m][0])[q] = v;
    }
    // stage B: 96 rows x 24 float4 over 128 threads (18 each)
    #pragma unroll
    for (int it = 0; it < 18; it++) {
        int idx = tid + it * GT;
        int j = idx / 24, q = idx % 24;
        float4 v = *(const float4*)(W + (size_t)j * DIM + q * 4);
        sB[j][2 * q + 0] = make_float2(v.x, v.y);
        sB[j][2 * q + 1] = make_float2(v.z, v.w);
    }
    __syncthreads();

    ull acc2[TM][TN];
    #pragma unroll
    for (int i = 0; i < TM; i++)
        #pragma unroll
        for (int j = 0; j < TN; j++) acc2[i][j] = 0ULL;

    #pragma unroll 4
    for (int kp = 0; kp < DIM / 2; kp++) {
        ull a2[TM], b2[TN];
        #pragma unroll
        for (int i = 0; i < TM; i++)
            a2[i] = *(const ull*)&sA[ty * TM + i][2 * kp];
        #pragma unroll
        for (int j = 0; j < TN; j++)
            b2[j] = *(const ull*)&sB[tx * TN + j][kp];
        #pragma unroll
        for (int i = 0; i < TM; i++)
            #pragma unroll
            for (int j = 0; j < TN; j++)
                ffma2(acc2[i][j], a2[i], b2[j]);
    }

    // epilogue
    const int colBase = tx * TN;
    #pragma unroll
    for (int i = 0; i < TM; i++) {
        int row = rowBase + ty * TM + i;
        if (row < N_NODES) {
            float r[TN];
            #pragma unroll
            for (int j = 0; j < TN; j++) {
                ull u = acc2[i][j];
                r[j] = __uint_as_float((unsigned)(u & 0xffffffffu)) +
                       __uint_as_float((unsigned)(u >> 32));
            }
            float* op = out + (size_t)row * DIM + colBase;
            #pragma unroll
            for (int j2 = 0; j2 < TN / 2; j2++) {
                float2 v;
                v.x = r[2 * j2 + 0] + bias[colBase + 2 * j2 + 0];
                v.y = r[2 * j2 + 1] + bias[colBase + 2 * j2 + 1];
                if (NEIGH) {
                    float2 prev = *(float2*)(op + 2 * j2);
                    v.x += prev.x;
                    v.y += prev.y;
                }
                *(float2*)(op + 2 * j2) = v;
            }
        }
    }
}

// ---------------------------------------------------------------------------
extern "C" void kernel_launch(void* const* d_in, const int* in_sizes, int n_in,
                              void* d_out, int out_size) {
    const float* x        = (const float*)d_in[0];
    const int*   ei       = (const int*)d_in[1];
    const float* W_self   = (const float*)d_in[2];
    const float* b_self   = (const float*)d_in[3];
    const float* W_neigh  = (const float*)d_in[4];
    const float* b_neigh  = (const float*)d_in[5];
    float*       out      = (float*)d_out;

    static cudaStream_t s2 = nullptr;
    static cudaEvent_t evFork = nullptr, evJoin = nullptr;
    static void* agg_ptr = nullptr;
    static void* deg_ptr = nullptr;
    static float* agg_f = nullptr;
    if (!s2) {
        cudaStreamCreateWithFlags(&s2, cudaStreamNonBlocking);
        cudaEventCreateWithFlags(&evFork, cudaEventDisableTiming);
        cudaEventCreateWithFlags(&evJoin, cudaEventDisableTiming);
        cudaGetSymbolAddress(&agg_ptr, g_agg);
        cudaGetSymbolAddress(&deg_ptr, g_deg);
        agg_f = (float*)agg_ptr;
    }

    // Fork: self-GEMM (independent of scatter) on s2.
    cudaEventRecord(evFork, 0);
    cudaStreamWaitEvent(s2, evFork, 0);
    gemm_half<false><<<GEMM_BLOCKS, GT, 0, s2>>>(x, W_self, b_self, out);

    // Main stream: zero scratch, then scatter.
    cudaMemsetAsync(agg_ptr, 0, (size_t)N_NODES * DIM * sizeof(float));
    cudaMemsetAsync(deg_ptr, 0, (size_t)N_NODES * sizeof(float));
    {
        long long total = (long long)N_EDGES * 24;
        int blocks = (int)((total + 255) / 256);
        scatter_kernel<<<blocks, 256>>>(x, ei);
    }

    // Join: neigh-GEMM needs scatter (stream order) + self-GEMM (event).
    cudaEventRecord(evJoin, s2);
    cudaStreamWaitEvent(0, evJoin, 0);
    gemm_half<true><<<GEMM_BLOCKS, GT>>>(agg_f, W_neigh, b_neigh, out);
}